// round 1
// baseline (speedup 1.0000x reference)
#include <cuda_runtime.h>

// CFConv fused kernel, fp32 baseline.
// h  = softplus_b05(rbf @ W1^T + b1)      [E,128]x[64,128]^T -> [E,64]
// g  = h @ W2^T + b2                      [E,64]x[64,64]^T   -> [E,64]
// out[dst[e]] += node_feats[src[e]] * g[e]
//
// Tiling: 64 edges x 64 dims per 256-thread block, BK=16, 4x4 register tile.

constexpr int R_DIM = 128;   // RBF dim (K of GEMM1)
constexpr int D_DIM = 64;    // feature dim
constexpr int BM = 64;       // edges per tile
constexpr int BN = 64;       // output dims per tile (== D_DIM)
constexpr int BK = 16;       // k-chunk

__global__ void zero_out_kernel(float4* out4, int n4) {
    int i = blockIdx.x * blockDim.x + threadIdx.x;
    if (i < n4) out4[i] = make_float4(0.f, 0.f, 0.f, 0.f);
}

__device__ __forceinline__ float softplus_b05(float x) {
    // (1/0.5)*log(1+exp(0.5*x)), linear when 0.5*x > 14
    float hx = 0.5f * x;
    return (hx > 14.0f) ? x : 2.0f * log1pf(__expf(hx));
}

__global__ __launch_bounds__(256, 2) void cfconv_kernel(
    const float* __restrict__ rbf,   // [E,128]
    const float* __restrict__ nf,    // [N,64]
    const int*   __restrict__ src,   // [E]
    const int*   __restrict__ dst,   // [E]
    const float* __restrict__ W1,    // [64,128]
    const float* __restrict__ b1,    // [64]
    const float* __restrict__ W2,    // [64,64]
    const float* __restrict__ b2,    // [64]
    float*       __restrict__ out,   // [N,64]
    int E)
{
    __shared__ float As[BK][BM];        // rbf chunk, k-major
    __shared__ float Bs[BK][BN];        // W chunk,  k-major
    __shared__ float sH[BM][BN + 4];    // softplus(h) tile
    __shared__ int   sSrc[BM];
    __shared__ int   sDst[BM];

    const int tid = threadIdx.x;
    const int tx  = tid & 15;           // n-direction (dims),  cols tx*4..+3
    const int ty  = tid >> 4;           // m-direction (edges), rows ty*4..+3
    const long e0 = (long)blockIdx.x * BM;

    if (tid < BM) {
        long e = e0 + tid;
        sSrc[tid] = (e < E) ? src[e] : 0;
        sDst[tid] = (e < E) ? dst[e] : 0;
    }

    // global-load mapping for smem tiles: each thread loads one float4
    const int le = tid >> 2;            // row 0..63 (edge for As, weight-row for Bs)
    const int lk = (tid & 3) << 2;      // k offset within chunk: 0,4,8,12
    const long eL = e0 + le;
    const bool evalid = (eL < E);

    float acc[4][4] = {};

    // ---------------- GEMM1: h = rbf @ W1^T ----------------
    for (int kc = 0; kc < R_DIM; kc += BK) {
        float4 av = evalid ? *(const float4*)(rbf + eL * R_DIM + kc + lk)
                           : make_float4(0.f, 0.f, 0.f, 0.f);
        float4 bv = *(const float4*)(W1 + (long)le * R_DIM + kc + lk);
        As[lk + 0][le] = av.x; As[lk + 1][le] = av.y;
        As[lk + 2][le] = av.z; As[lk + 3][le] = av.w;
        Bs[lk + 0][le] = bv.x; Bs[lk + 1][le] = bv.y;
        Bs[lk + 2][le] = bv.z; Bs[lk + 3][le] = bv.w;
        __syncthreads();
        #pragma unroll
        for (int k = 0; k < BK; k++) {
            float4 a4 = *(const float4*)&As[k][ty << 2];
            float4 b4 = *(const float4*)&Bs[k][tx << 2];
            acc[0][0] += a4.x * b4.x; acc[0][1] += a4.x * b4.y;
            acc[0][2] += a4.x * b4.z; acc[0][3] += a4.x * b4.w;
            acc[1][0] += a4.y * b4.x; acc[1][1] += a4.y * b4.y;
            acc[1][2] += a4.y * b4.z; acc[1][3] += a4.y * b4.w;
            acc[2][0] += a4.z * b4.x; acc[2][1] += a4.z * b4.y;
            acc[2][2] += a4.z * b4.z; acc[2][3] += a4.z * b4.w;
            acc[3][0] += a4.w * b4.x; acc[3][1] += a4.w * b4.y;
            acc[3][2] += a4.w * b4.z; acc[3][3] += a4.w * b4.w;
        }
        __syncthreads();
    }

    // bias + softplus, stage h tile in smem
    {
        float4 b1v = *(const float4*)(b1 + (tx << 2));
        #pragma unroll
        for (int i = 0; i < 4; i++) {
            int r = (ty << 2) + i;
            float4 h4;
            h4.x = softplus_b05(acc[i][0] + b1v.x);
            h4.y = softplus_b05(acc[i][1] + b1v.y);
            h4.z = softplus_b05(acc[i][2] + b1v.z);
            h4.w = softplus_b05(acc[i][3] + b1v.w);
            *(float4*)&sH[r][tx << 2] = h4;
        }
    }
    __syncthreads();

    // ---------------- GEMM2: g = h @ W2^T ----------------
    float acc2[4][4] = {};
    for (int kc = 0; kc < D_DIM; kc += BK) {
        float4 bv = *(const float4*)(W2 + (long)le * D_DIM + kc + lk);
        Bs[lk + 0][le] = bv.x; Bs[lk + 1][le] = bv.y;
        Bs[lk + 2][le] = bv.z; Bs[lk + 3][le] = bv.w;
        __syncthreads();
        #pragma unroll
        for (int k = 0; k < BK; k++) {
            float a_[4];
            #pragma unroll
            for (int i = 0; i < 4; i++) a_[i] = sH[(ty << 2) + i][kc + k];
            float4 b4 = *(const float4*)&Bs[k][tx << 2];
            #pragma unroll
            for (int i = 0; i < 4; i++) {
                acc2[i][0] += a_[i] * b4.x; acc2[i][1] += a_[i] * b4.y;
                acc2[i][2] += a_[i] * b4.z; acc2[i][3] += a_[i] * b4.w;
            }
        }
        __syncthreads();
    }

    // ---------------- epilogue: gate by nf[src], atomic-scatter to out[dst] ----
    {
        float4 b2v = *(const float4*)(b2 + (tx << 2));
        #pragma unroll
        for (int i = 0; i < 4; i++) {
            int r = (ty << 2) + i;
            long e = e0 + r;
            if (e < E) {
                int s  = sSrc[r];
                int dd = sDst[r];
                float4 nf4 = *(const float4*)(nf + (long)s * D_DIM + (tx << 2));
                float m0 = (acc2[i][0] + b2v.x) * nf4.x;
                float m1 = (acc2[i][1] + b2v.y) * nf4.y;
                float m2 = (acc2[i][2] + b2v.z) * nf4.z;
                float m3 = (acc2[i][3] + b2v.w) * nf4.w;
                float* op = out + (long)dd * D_DIM + (tx << 2);
                atomicAdd(op + 0, m0);
                atomicAdd(op + 1, m1);
                atomicAdd(op + 2, m2);
                atomicAdd(op + 3, m3);
            }
        }
    }
}

extern "C" void kernel_launch(void* const* d_in, const int* in_sizes, int n_in,
                              void* d_out, int out_size) {
    const float* rbf = (const float*)d_in[0];
    const float* nf  = (const float*)d_in[1];
    const int*   src = (const int*)d_in[2];
    const int*   dst = (const int*)d_in[3];
    const float* W1  = (const float*)d_in[4];
    const float* b1  = (const float*)d_in[5];
    const float* W2  = (const float*)d_in[6];
    const float* b2  = (const float*)d_in[7];
    float* out = (float*)d_out;

    const int E = in_sizes[2];          // number of edges (src count)

    // zero the output (harness poisons it)
    int n4 = out_size / 4;
    zero_out_kernel<<<(n4 + 255) / 256, 256>>>((float4*)out, n4);

    int grid = (E + BM - 1) / BM;
    cfconv_kernel<<<grid, 256>>>(rbf, nf, src, dst, W1, b1, W2, b2, out, E);
}